// round 9
// baseline (speedup 1.0000x reference)
#include <cuda_runtime.h>
#include <cuda_bf16.h>

// Problem constants
#define BB 32
#define CC_ 256
#define OO 256
#define HH 56
#define WW 56
#define CHK 4
#define HW (HH*WW)

// Conv tiling constants
#define TOC 32      // output channels per block
#define CCH 16      // input channels per smem chunk
#define NOCB (OO/TOC)       // 8 oc blocks
#define NCCH (CC_/CCH)      // 16 channel chunks

// ---------------- scratch (device globals: allocation-free) ----------------
__device__ float g_pooled[BB*CC_];
__device__ float g_h[BB*CC_];
__device__ float g_kern[BB*CC_*CHK];
// dyn_w stored in the conv kernel's tiled layout:
// [b][ocb(8)][cchunk(16)][c_local(16)][k(9)][oc_local(32)]
__device__ float g_dynw[(size_t)BB*OO*CC_*9];

// ---------------- packed f32x2 helpers ----------------
__device__ __forceinline__ double ffma2(double a, double b, double c) {
    double d;
    asm("fma.rn.f32x2 %0, %1, %2, %3;" : "=d"(d) : "d"(a), "d"(b), "d"(c));
    return d;
}
__device__ __forceinline__ double pack2(float lo, float hi) {
    double d;
    asm("mov.b64 %0, {%1, %2};" : "=d"(d) : "f"(lo), "f"(hi));
    return d;
}
__device__ __forceinline__ float2 unpack2(double d) {
    float2 v;
    asm("mov.b64 {%0, %1}, %2;" : "=f"(v.x), "=f"(v.y) : "d"(d));
    return v;
}

// ---------------- kernel 1: global average pool ----------------
__global__ __launch_bounds__(128) void pool_kernel(const float* __restrict__ x) {
    int bc = blockIdx.x;                         // 0 .. B*C-1
    const float4* xp = (const float4*)(x + (size_t)bc * HW);
    float s = 0.f;
    for (int i = threadIdx.x; i < HW/4; i += 128) {
        float4 v = xp[i];
        s += (v.x + v.y) + (v.z + v.w);
    }
    for (int off = 16; off > 0; off >>= 1)
        s += __shfl_down_sync(0xffffffffu, s, off);
    __shared__ float red[4];
    if ((threadIdx.x & 31) == 0) red[threadIdx.x >> 5] = s;
    __syncthreads();
    if (threadIdx.x == 0) {
        float t = red[0] + red[1] + red[2] + red[3];
        g_pooled[bc] = t * (1.0f / (float)HW);
    }
}

// ---------------- kernel 2: h = relu(pooled @ fc1_w^T) ----------------
__global__ __launch_bounds__(256) void fc1_kernel(const float* __restrict__ fc1_w) {
    int b = blockIdx.x;
    int i = threadIdx.x;
    __shared__ float sp[CC_];
    sp[i] = g_pooled[b*CC_ + i];
    __syncthreads();
    const float* wr = fc1_w + (size_t)i * CC_;
    float s = 0.f;
    #pragma unroll 8
    for (int k = 0; k < CC_; ++k) s = fmaf(sp[k], wr[k], s);
    g_h[b*CC_ + i] = fmaxf(s, 0.f);
}

// ---------------- kernel 3: kern = h @ fc2_w^T + fc2_b ----------------
__global__ __launch_bounds__(1024) void fc2_kernel(const float* __restrict__ fc2_w,
                                                   const float* __restrict__ fc2_b) {
    int b = blockIdx.x;
    int j = threadIdx.x;
    __shared__ float sh[CC_];
    if (j < CC_) sh[j] = g_h[b*CC_ + j];
    __syncthreads();
    const float* wr = fc2_w + (size_t)j * CC_;
    float s = fc2_b[j];
    #pragma unroll 8
    for (int k = 0; k < CC_; ++k) s = fmaf(sh[k], wr[k], s);
    g_kern[b*(CC_*CHK) + j] = s;
}

// ---------------- kernel 4: dyn_w = sigmoid(einsum) * weight ----------------
__global__ __launch_bounds__(256) void dynw_kernel(const float* __restrict__ cog,
                                                   const float* __restrict__ weight) {
    int idx = blockIdx.x * 256 + threadIdx.x;     // < B*O*C*9
    int ocl = idx & 31;
    int t0  = idx >> 5;
    int k   = t0 % 9;
    int t1  = t0 / 9;
    int cl  = t1 & 15;
    int t2  = t1 >> 4;
    int cch = t2 & 15;
    int t3  = t2 >> 4;
    int ocb = t3 & 7;
    int b   = t3 >> 3;

    int o = ocb*TOC + ocl;
    int c = cch*CCH + cl;

    const float* kp = g_kern + b*(CC_*CHK) + c*CHK;
    float cw = 0.f;
    #pragma unroll
    for (int t = 0; t < CHK; ++t)
        cw = fmaf(kp[t], cog[(o*CHK + t)*9 + k], cw);
    float sg = __fdividef(1.0f, 1.0f + __expf(-cw));
    g_dynw[idx] = sg * weight[((size_t)o*CC_ + c)*9 + k];
}

// ---------------- kernel 5: per-sample 3x3 conv (packed f32x2) ----------------
// Block: 128 threads. Tile: 32 oc x 8x8 px. Thread: 4 oc x 2 rows x (2-px pair).
__global__ __launch_bounds__(128) void conv_kernel(const float* __restrict__ x,
                                                   float* __restrict__ out) {
    const int sp  = blockIdx.x;       // 0..48 spatial tile (7x7)
    const int ocb = blockIdx.y;       // 0..7
    const int b   = blockIdx.z;       // 0..31
    const int ty0 = (sp / 7) * 8;
    const int tx0 = (sp % 7) * 8;

    const int tid    = threadIdx.x;
    const int oc_sub = tid >> 4;      // 0..7
    const int px_sub = tid & 15;
    const int pr2    = (px_sub >> 2) * 2;   // 0,2,4,6
    const int pc2    = (px_sub & 3) * 2;    // 0,2,4,6
    const int oc4    = oc_sub * 4;

    __shared__ float xs[CCH][10][12];       // padded rows -> conflict-free
    __shared__ float wsd[CCH*9*64];         // duplicated weights [c][k][oc*2]

    // acc[oc_i][dy] : packed pair over (dx=0, dx=1)
    double acc[4][2];
    #pragma unroll
    for (int i = 0; i < 4; ++i) { acc[i][0] = 0.0; acc[i][1] = 0.0; }

    const float* xb = x + (size_t)b * CC_ * HW;
    const float4* wbase = (const float4*)(g_dynw + ((size_t)(b*NOCB + ocb) * NCCH) * (CCH*9*TOC));

    for (int cc = 0; cc < NCCH; ++cc) {
        // --- stage x halo: 16 ch x 10 x 10 (zero-padded borders) ---
        for (int i = tid; i < CCH*100; i += 128) {
            int c  = i / 100;
            int r  = i - c*100;
            int yy = r / 10;
            int xx = r - yy*10;
            int gy = ty0 - 1 + yy;
            int gx = tx0 - 1 + xx;
            float v = 0.f;
            if ((unsigned)gy < (unsigned)HH && (unsigned)gx < (unsigned)WW)
                v = xb[(cc*CCH + c)*HW + gy*WW + gx];
            xs[c][yy][xx] = v;
        }
        // --- stage duplicated weights: (w0,w0,w1,w1)(w2,w2,w3,w3) ---
        const float4* wsrc = wbase + (size_t)cc * (CCH*9*TOC/4);
        #pragma unroll
        for (int i = 0; i < 9; ++i) {           // 1152 source float4 / 128 threads
            int j = tid + i*128;
            float4 w = wsrc[j];
            int f  = j * 4;
            int ck = f >> 5;                    // (c*9 + k)
            int oc = f & 31;
            float4* d0 = (float4*)&wsd[ck*64 + oc*2];
            d0[0] = make_float4(w.x, w.x, w.y, w.y);
            d0[1] = make_float4(w.z, w.z, w.w, w.w);
        }
        __syncthreads();

        #pragma unroll 4
        for (int c = 0; c < CCH; ++c) {
            // x pairs: xp[row r][kx] = (x[pc2+kx], x[pc2+kx+1]) for rows pr2+r
            double xp[4][3];
            #pragma unroll
            for (int r = 0; r < 4; ++r) {
                float2 a  = *(const float2*)&xs[c][pr2 + r][pc2];
                float2 b2 = *(const float2*)&xs[c][pr2 + r][pc2 + 2];
                xp[r][0] = pack2(a.x, a.y);
                xp[r][1] = pack2(a.y, b2.x);
                xp[r][2] = pack2(b2.x, b2.y);
            }
            const int base = c*(9*64) + oc4*2;
            #pragma unroll
            for (int ky = 0; ky < 3; ++ky) {
                #pragma unroll
                for (int kx = 0; kx < 3; ++kx) {
                    const int kof = base + (ky*3 + kx)*64;
                    double2 wA = *(const double2*)&wsd[kof];        // (w0,w0),(w1,w1)
                    double2 wB = *(const double2*)&wsd[kof + 4];    // (w2,w2),(w3,w3)
                    acc[0][0] = ffma2(wA.x, xp[ky    ][kx], acc[0][0]);
                    acc[0][1] = ffma2(wA.x, xp[ky + 1][kx], acc[0][1]);
                    acc[1][0] = ffma2(wA.y, xp[ky    ][kx], acc[1][0]);
                    acc[1][1] = ffma2(wA.y, xp[ky + 1][kx], acc[1][1]);
                    acc[2][0] = ffma2(wB.x, xp[ky    ][kx], acc[2][0]);
                    acc[2][1] = ffma2(wB.x, xp[ky + 1][kx], acc[2][1]);
                    acc[3][0] = ffma2(wB.y, xp[ky    ][kx], acc[3][0]);
                    acc[3][1] = ffma2(wB.y, xp[ky + 1][kx], acc[3][1]);
                }
            }
        }
        __syncthreads();
    }

    // --- epilogue: unpack pairs, float2 stores ---
    #pragma unroll
    for (int i = 0; i < 4; ++i) {
        int oc = ocb*TOC + oc4 + i;
        float* op = out + (size_t)(b*OO + oc) * HW;
        #pragma unroll
        for (int dy = 0; dy < 2; ++dy) {
            float2 v = unpack2(acc[i][dy]);
            *(float2*)&op[(ty0 + pr2 + dy)*WW + tx0 + pc2] = v;
        }
    }
}

// ---------------- launcher ----------------
extern "C" void kernel_launch(void* const* d_in, const int* in_sizes, int n_in,
                              void* d_out, int out_size) {
    const float* x     = (const float*)d_in[0];
    const float* fc1_w = (const float*)d_in[1];
    const float* fc2_w = (const float*)d_in[2];
    const float* fc2_b = (const float*)d_in[3];
    const float* cog   = (const float*)d_in[4];
    const float* weight= (const float*)d_in[5];
    float* out = (float*)d_out;

    pool_kernel<<<BB*CC_, 128>>>(x);
    fc1_kernel<<<BB, 256>>>(fc1_w);
    fc2_kernel<<<BB, 1024>>>(fc2_w, fc2_b);
    dynw_kernel<<<(BB*OO*CC_*9)/256, 256>>>(cog, weight);
    dim3 grid(49, NOCB, BB);
    conv_kernel<<<grid, 128>>>(x, out);
}

// round 12
// speedup vs baseline: 5.0399x; 5.0399x over previous
#include <cuda_runtime.h>
#include <cuda_fp16.h>
#include <stdint.h>

// Problem constants
#define BB 32
#define CC_ 256
#define OO 256
#define HH 56
#define WW 56
#define CHK 4
#define HW (HH*WW)          // 3136

// ---------------- scratch (device globals: allocation-free) ----------------
__device__ float g_pooled[BB*CC_];
__device__ float g_h[BB*CC_];
__device__ float g_kern[BB*CC_*CHK];
// x transposed+converted: [b][px][c] fp16
__device__ __align__(16) __half g_xh[(size_t)BB*HW*CC_];
// dyn weights fp16: [b][tap(9)][oc(256)][c(256)], stored as uint32 c-pairs
__device__ __align__(16) uint32_t g_w[(size_t)BB*9*OO*(CC_/2)];

// ---------------- PTX helpers ----------------
__device__ __forceinline__ uint32_t smem_u32(const void* p) {
    uint32_t a;
    asm("{ .reg .u64 t; cvta.to.shared.u64 t, %1; cvt.u32.u64 %0, t; }" : "=r"(a) : "l"(p));
    return a;
}
__device__ __forceinline__ void cp_async16(uint32_t dst, const void* src) {
    asm volatile("cp.async.ca.shared.global [%0], [%1], 16;" :: "r"(dst), "l"(src));
}
__device__ __forceinline__ void st_smem_zero16(uint32_t dst) {
    asm volatile("st.shared.v4.u32 [%0], {%1,%1,%1,%1};" :: "r"(dst), "r"(0u));
}
__device__ __forceinline__ void ldm4(uint32_t* r, uint32_t addr) {
    asm volatile("ldmatrix.sync.aligned.m8n8.x4.shared.b16 {%0,%1,%2,%3}, [%4];"
                 : "=r"(r[0]), "=r"(r[1]), "=r"(r[2]), "=r"(r[3]) : "r"(addr));
}
__device__ __forceinline__ void mma16816(float* d, const uint32_t* a, uint32_t b0, uint32_t b1) {
    asm volatile("mma.sync.aligned.m16n8k16.row.col.f32.f16.f16.f32 "
                 "{%0,%1,%2,%3}, {%4,%5,%6,%7}, {%8,%9}, {%0,%1,%2,%3};"
                 : "+f"(d[0]), "+f"(d[1]), "+f"(d[2]), "+f"(d[3])
                 : "r"(a[0]), "r"(a[1]), "r"(a[2]), "r"(a[3]), "r"(b0), "r"(b1));
}

// ---------------- kernel 1: global average pool ----------------
__global__ __launch_bounds__(128) void pool_kernel(const float* __restrict__ x) {
    int bc = blockIdx.x;
    const float4* xp = (const float4*)(x + (size_t)bc * HW);
    float s = 0.f;
    for (int i = threadIdx.x; i < HW/4; i += 128) {
        float4 v = xp[i];
        s += (v.x + v.y) + (v.z + v.w);
    }
    for (int off = 16; off > 0; off >>= 1)
        s += __shfl_down_sync(0xffffffffu, s, off);
    __shared__ float red[4];
    if ((threadIdx.x & 31) == 0) red[threadIdx.x >> 5] = s;
    __syncthreads();
    if (threadIdx.x == 0) {
        float t = red[0] + red[1] + red[2] + red[3];
        g_pooled[bc] = t * (1.0f / (float)HW);
    }
}

// ---------------- kernel 2: h = relu(pooled @ fc1_w^T) ----------------
__global__ __launch_bounds__(256) void fc1_kernel(const float* __restrict__ fc1_w) {
    int b = blockIdx.x;
    int i = threadIdx.x;
    __shared__ float sp[CC_];
    sp[i] = g_pooled[b*CC_ + i];
    __syncthreads();
    const float* wr = fc1_w + (size_t)i * CC_;
    float s = 0.f;
    #pragma unroll 8
    for (int k = 0; k < CC_; ++k) s = fmaf(sp[k], wr[k], s);
    g_h[b*CC_ + i] = fmaxf(s, 0.f);
}

// ---------------- kernel 3: kern = h @ fc2_w^T + fc2_b ----------------
__global__ __launch_bounds__(1024) void fc2_kernel(const float* __restrict__ fc2_w,
                                                   const float* __restrict__ fc2_b) {
    int b = blockIdx.x;
    int j = threadIdx.x;
    __shared__ float sh[CC_];
    if (j < CC_) sh[j] = g_h[b*CC_ + j];
    __syncthreads();
    const float* wr = fc2_w + (size_t)j * CC_;
    float s = fc2_b[j];
    #pragma unroll 8
    for (int k = 0; k < CC_; ++k) s = fmaf(sh[k], wr[k], s);
    g_kern[b*(CC_*CHK) + j] = s;
}

// ---------------- kernel 4: dyn weights -> fp16, layout [b][tap][oc][c] ----------------
__global__ __launch_bounds__(256) void dynw_kernel(const float* __restrict__ cog,
                                                   const float* __restrict__ weight) {
    int idx = blockIdx.x * 256 + threadIdx.x;      // < 32*9*256*128 = 9,437,184
    int c2  = idx & 127;
    int r   = idx >> 7;
    int o   = r & 255;
    int r2  = r >> 8;
    int tap = r2 % 9;
    int b   = r2 / 9;
    int c0  = c2 * 2;

    const float4* kp = (const float4*)(g_kern + b*(CC_*CHK) + c0*CHK);
    float4 ka = kp[0];
    float4 kb = kp[1];
    float cg0 = cog[(o*CHK + 0)*9 + tap];
    float cg1 = cog[(o*CHK + 1)*9 + tap];
    float cg2 = cog[(o*CHK + 2)*9 + tap];
    float cg3 = cog[(o*CHK + 3)*9 + tap];
    float cw0 = ka.x*cg0 + ka.y*cg1 + ka.z*cg2 + ka.w*cg3;
    float cw1 = kb.x*cg0 + kb.y*cg1 + kb.z*cg2 + kb.w*cg3;
    float w0 = weight[((size_t)o*CC_ + c0)*9 + tap];
    float w1 = weight[((size_t)o*CC_ + c0 + 1)*9 + tap];
    float v0 = __fdividef(1.0f, 1.0f + __expf(-cw0)) * w0;
    float v1 = __fdividef(1.0f, 1.0f + __expf(-cw1)) * w1;

    __half h0 = __float2half_rn(v0);
    __half h1 = __float2half_rn(v1);
    g_w[idx] = ((uint32_t)__half_as_ushort(h1) << 16) | __half_as_ushort(h0);
}

// ---------------- kernel 4b: x fp32 [b][c][hw] -> fp16 [b][hw][c] ----------------
__global__ __launch_bounds__(256) void xcvt_kernel(const float* __restrict__ x) {
    const int pxt = blockIdx.x * 64;     // 49 tiles
    const int ct  = blockIdx.y * 64;     // 4 tiles
    const int b   = blockIdx.z;
    __shared__ __half t[64][72];         // [c][px], padded

    int tid = threadIdx.x;
    int cl = tid >> 2;           // 0..63
    int pg = tid & 3;            // 0..3  (16 px each)
    const float4* src = (const float4*)(x + ((size_t)(b*CC_ + ct + cl)*HW + pxt + pg*16));
    #pragma unroll
    for (int u = 0; u < 4; ++u) {
        float4 v = src[u];
        t[cl][pg*16 + u*4 + 0] = __float2half_rn(v.x);
        t[cl][pg*16 + u*4 + 1] = __float2half_rn(v.y);
        t[cl][pg*16 + u*4 + 2] = __float2half_rn(v.z);
        t[cl][pg*16 + u*4 + 3] = __float2half_rn(v.w);
    }
    __syncthreads();
    int pl = tid >> 2;           // px row 0..63
    int cg = tid & 3;            // 16 c each
    __half* dst = g_xh + ((size_t)b*HW + pxt + pl)*CC_ + ct + cg*16;
    uint32_t buf[8];
    #pragma unroll
    for (int u = 0; u < 8; ++u) {
        __half lo = t[cg*16 + u*2][pl];
        __half hi = t[cg*16 + u*2 + 1][pl];
        buf[u] = ((uint32_t)__half_as_ushort(hi) << 16) | __half_as_ushort(lo);
    }
    uint4* d4 = (uint4*)dst;
    d4[0] = make_uint4(buf[0], buf[1], buf[2], buf[3]);
    d4[1] = make_uint4(buf[4], buf[5], buf[6], buf[7]);
}

// ---------------- kernel 5: fp16 mma.sync implicit-GEMM conv ----------------
// Grid (25 px-tiles, 2 oc-halves, 32 b). Block 256 thr = 8 warps.
// Block tile 128 px x 128 oc; warp tile 64 px x 32 oc. K = 9 taps x 4 chunks x 64 c.
#define AB_BYTES 16384                 // 128 rows x 128B
#define CONV_SMEM (4*AB_BYTES)         // A0,A1,B0,B1 = 64KB

__global__ __launch_bounds__(256, 2)
void conv_mma(float* __restrict__ out) {
    extern __shared__ char smem[];
    const uint32_t sb = smem_u32(smem);
    const int tid = threadIdx.x;
    const int p0  = blockIdx.x * 128;
    const int ocb = blockIdx.y * 128;
    const int b   = blockIdx.z;

    // staging thread mapping: row r = tid>>1, half = tid&1 (4 x 16B units)
    const int sr   = tid >> 1;
    const int shalf= tid & 1;
    const int sp_  = p0 + sr;
    const int spy  = sp_ / WW;
    const int spx  = sp_ - spy * WW;
    const uint32_t sdst_row = sr*128 + shalf*64;
    const __half* xrow_base = g_xh + ((size_t)b*HW + sp_)*CC_;
    const uint32_t* wrow_base = g_w + ((size_t)(b*9))*OO*128 + (size_t)(ocb + sr)*128;

    // per-iteration staging
    auto stage = [&](int i) {
        int tap = i >> 2;        // 0..8
        int cch = i & 3;         // 0..3
        int j   = i & 1;
        int dy = tap/3 - 1, dx = tap%3 - 1;
        // A
        {
            bool valid = (sp_ < HW) && ((unsigned)(spy+dy) < HH) && ((unsigned)(spx+dx) < WW);
            uint32_t abuf = sb + j*AB_BYTES;
            const char* src = (const char*)(xrow_base + (dy*WW + dx)*CC_ + cch*64 + shalf*32);
            #pragma unroll
            for (int q = 0; q < 4; ++q) {
                uint32_t off = sdst_row + q*16;
                uint32_t dst = abuf + (off ^ ((off >> 3) & 0x70));
                if (valid) cp_async16(dst, src + q*16);
                else       st_smem_zero16(dst);
            }
        }
        // B
        {
            uint32_t bbuf = sb + 2*AB_BYTES + j*AB_BYTES;
            const char* src = (const char*)(wrow_base + (size_t)tap*OO*128 + cch*32 + shalf*16);
            #pragma unroll
            for (int q = 0; q < 4; ++q) {
                uint32_t off = sdst_row + q*16;
                uint32_t dst = bbuf + (off ^ ((off >> 3) & 0x70));
                cp_async16(dst, src + q*16);
            }
        }
    };

    // compute lane constants
    const int wid  = tid >> 5;
    const int lane = tid & 31;
    const int wm = (wid & 1) * 64;          // warp px offset
    const int wn = (wid >> 1) * 32;         // warp oc offset
    const uint32_t xm   = (uint32_t)(lane & 7) << 4;          // swizzle xor (rows mult of 8)
    const uint32_t arow = (uint32_t)(wm + (lane & 15)) * 128;
    const uint32_t acol = (uint32_t)((lane >> 4) << 4);
    const uint32_t brow = (uint32_t)(wn + ((lane >> 4) << 3) + (lane & 7)) * 128;
    const uint32_t bcol = (uint32_t)(((lane >> 3) & 1) << 4);

    float d[16][4];
    #pragma unroll
    for (int i = 0; i < 16; ++i)
        #pragma unroll
        for (int k = 0; k < 4; ++k) d[i][k] = 0.f;

    stage(0);
    asm volatile("cp.async.commit_group;" ::: "memory");

    for (int i = 0; i < 36; ++i) {
        if (i < 35) {
            stage(i + 1);
            asm volatile("cp.async.commit_group;" ::: "memory");
            asm volatile("cp.async.wait_group 1;" ::: "memory");
        } else {
            asm volatile("cp.async.wait_group 0;" ::: "memory");
        }
        __syncthreads();

        const int j = i & 1;
        const uint32_t abuf = sb + j*AB_BYTES;
        const uint32_t bbuf = sb + 2*AB_BYTES + j*AB_BYTES;
        #pragma unroll
        for (int ks = 0; ks < 4; ++ks) {
            uint32_t bfr[2][4];
            uint32_t bco = (uint32_t)(ks*32 + bcol) ^ xm;
            ldm4(bfr[0], bbuf + brow + bco);
            ldm4(bfr[1], bbuf + brow + 16*128 + bco);
            uint32_t aco = (uint32_t)(ks*32 + acol) ^ xm;
            #pragma unroll
            for (int mi = 0; mi < 4; ++mi) {
                uint32_t afr[4];
                ldm4(afr, abuf + arow + (uint32_t)mi*2048 + aco);
                mma16816(d[mi*4 + 0], afr, bfr[0][0], bfr[0][1]);
                mma16816(d[mi*4 + 1], afr, bfr[0][2], bfr[0][3]);
                mma16816(d[mi*4 + 2], afr, bfr[1][0], bfr[1][1]);
                mma16816(d[mi*4 + 3], afr, bfr[1][2], bfr[1][3]);
            }
        }
        __syncthreads();
    }

    // epilogue
    const int t4 = lane >> 2;        // 0..7
    const int tm = lane & 3;         // 0..3
    #pragma unroll
    for (int mi = 0; mi < 4; ++mi) {
        int r0 = p0 + wm + mi*16 + t4;
        int r1 = r0 + 8;
        bool v0 = r0 < HW, v1 = r1 < HW;
        #pragma unroll
        for (int ni = 0; ni < 4; ++ni) {
            int oc = ocb + wn + ni*8 + tm*2;
            float* o0 = out + ((size_t)(b*OO + oc))*HW;
            float* o1 = o0 + HW;
            const float* dd = d[mi*4 + ni];
            if (v0) { o0[r0] = dd[0]; o1[r0] = dd[1]; }
            if (v1) { o0[r1] = dd[2]; o1[r1] = dd[3]; }
        }
    }
}

// ---------------- launcher ----------------
extern "C" void kernel_launch(void* const* d_in, const int* in_sizes, int n_in,
                              void* d_out, int out_size) {
    const float* x     = (const float*)d_in[0];
    const float* fc1_w = (const float*)d_in[1];
    const float* fc2_w = (const float*)d_in[2];
    const float* fc2_b = (const float*)d_in[3];
    const float* cog   = (const float*)d_in[4];
    const float* weight= (const float*)d_in[5];
    float* out = (float*)d_out;

    pool_kernel<<<BB*CC_, 128>>>(x);
    fc1_kernel<<<BB, 256>>>(fc1_w);
    fc2_kernel<<<BB, 1024>>>(fc2_w, fc2_b);
    dynw_kernel<<<(BB*9*OO*(CC_/2))/256, 256>>>(cog, weight);
    {
        dim3 g(HW/64, CC_/64, BB);
        xcvt_kernel<<<g, 256>>>(x);
    }
    cudaFuncSetAttribute(conv_mma, cudaFuncAttributeMaxDynamicSharedMemorySize, CONV_SMEM);
    dim3 grid((HW + 127)/128, OO/128, BB);   // 25 x 2 x 32
    conv_mma<<<grid, 256, CONV_SMEM>>>(out);
}